// round 13
// baseline (speedup 1.0000x reference)
#include <cuda_runtime.h>
#include <cuda_bf16.h>
#include <math.h>
#include <stdint.h>

#define B    32
#define S    512
#define DIM  1024
#define HID  4096
#define E    8
#define TOPK 2
#define CAP  8
#define NPAIR (B*TOPK)

#define KC   32                 // K chunk (bf16 elems)
#define NT   256                // N tile
#define A_STRIDE 80             // bytes per A row in smem
#define B_STRIDE 528            // bytes per B row in smem (256*2 padded)
#define A_MAT   10240           // 128 rows * 80B
#define B_MAT   16896           // 32 rows * 528B
#define A_SZ    20480           // 2 * A_MAT
#define STAGE   54272           // A hi/lo + B hi/lo
#define NSTAGE  4
#define SMEM_DYN (NSTAGE * STAGE)

// ---------------- device scratch -------------------------------------------
__device__ float g_ri[B * DIM];
__device__ int   g_sample[E * CAP];
__device__ float g_gate[E * CAP];
__device__ int   g_count[E];
__device__ __nv_bfloat16 g_xc_hi[(size_t)B * S * DIM];
__device__ __nv_bfloat16 g_xc_lo[(size_t)B * S * DIM];
__device__ __nv_bfloat16 g_w1_hi[(size_t)E * DIM * HID];   // [e][k][n]
__device__ __nv_bfloat16 g_w1_lo[(size_t)E * DIM * HID];
__device__ __nv_bfloat16 g_w2_hi[(size_t)E * HID * DIM];   // [e][k][n]
__device__ __nv_bfloat16 g_w2_lo[(size_t)E * HID * DIM];
__device__ __nv_bfloat16 g_h_hi[(size_t)E * CAP * S * HID];
__device__ __nv_bfloat16 g_h_lo[(size_t)E * CAP * S * HID];

// ---------------- PTX helpers ----------------------------------------------
__device__ __forceinline__ uint32_t smem_u32(const void* p) {
    uint32_t a;
    asm("{ .reg .u64 t; cvta.to.shared.u64 t, %1; cvt.u32.u64 %0, t; }" : "=r"(a) : "l"(p));
    return a;
}
__device__ __forceinline__ void cp16(uint32_t dst, const void* src) {
    asm volatile("cp.async.cg.shared.global [%0], [%1], 16;" :: "r"(dst), "l"(src));
}
#define CP_COMMIT()  asm volatile("cp.async.commit_group;" ::: "memory")
#define CP_WAIT_2()  asm volatile("cp.async.wait_group 2;" ::: "memory")
#define CP_WAIT_1()  asm volatile("cp.async.wait_group 1;" ::: "memory")
#define CP_WAIT_0()  asm volatile("cp.async.wait_group 0;" ::: "memory")

__device__ __forceinline__ void ldsm_x4(uint32_t a, uint32_t r[4]) {
    asm volatile("ldmatrix.sync.aligned.m8n8.x4.shared.b16 {%0,%1,%2,%3}, [%4];"
                 : "=r"(r[0]), "=r"(r[1]), "=r"(r[2]), "=r"(r[3]) : "r"(a));
}
__device__ __forceinline__ void ldsm_x4t(uint32_t a, uint32_t r[4]) {
    asm volatile("ldmatrix.sync.aligned.m8n8.x4.trans.shared.b16 {%0,%1,%2,%3}, [%4];"
                 : "=r"(r[0]), "=r"(r[1]), "=r"(r[2]), "=r"(r[3]) : "r"(a));
}
__device__ __forceinline__ void mma16816(float c[4], const uint32_t a[4],
                                         uint32_t b0, uint32_t b1) {
    asm volatile("mma.sync.aligned.m16n8k16.row.col.f32.bf16.bf16.f32 "
                 "{%0,%1,%2,%3},{%4,%5,%6,%7},{%8,%9},{%0,%1,%2,%3};"
                 : "+f"(c[0]), "+f"(c[1]), "+f"(c[2]), "+f"(c[3])
                 : "r"(a[0]), "r"(a[1]), "r"(a[2]), "r"(a[3]), "r"(b0), "r"(b1));
}
__device__ __forceinline__ void red_add_v2(float* p, float v0, float v1) {
    asm volatile("red.global.add.v2.f32 [%0], {%1, %2};"
                 :: "l"(p), "f"(v0), "f"(v1) : "memory");
}

// ---------------- kernel: ri = mean over sequence ---------------------------
__global__ void ri_kernel(const float* __restrict__ rin) {
    int idx = blockIdx.x * blockDim.x + threadIdx.x;
    if (idx >= B * DIM) return;
    int b = idx / DIM, d = idx % DIM;
    const float* p = rin + (size_t)b * S * DIM + d;
    float acc = 0.f;
    #pragma unroll 8
    for (int s = 0; s < S; ++s) acc += p[(size_t)s * DIM];
    g_ri[idx] = acc * (1.0f / S);
}

// ---------------- kernel: router + top-2 + capacity (1024 thr) --------------
__global__ void __launch_bounds__(1024) router_kernel(
        const float* __restrict__ noise,
        const float* __restrict__ Wg, const float* __restrict__ bg,
        const float* __restrict__ Wn, const float* __restrict__ bn) {
    __shared__ float s_noisy[B][E];
    __shared__ int   s_fe[NPAIR];
    __shared__ float s_fg[NPAIR];
    const int t = threadIdx.x;
    {
        const int pair = t >> 2, q = t & 3;
        const int b = pair / E, e = pair % E;
        const float* ri = g_ri + b * DIM + q * 256;
        float lg = 0.f, ln = 0.f;
        #pragma unroll 8
        for (int d = 0; d < 256; ++d) {
            float r = ri[d];
            int col = (q * 256 + d) * E + e;
            lg = fmaf(r, Wg[col], lg);
            ln = fmaf(r, Wn[col], ln);
        }
        lg += __shfl_xor_sync(0xFFFFFFFFu, lg, 1);
        lg += __shfl_xor_sync(0xFFFFFFFFu, lg, 2);
        ln += __shfl_xor_sync(0xFFFFFFFFu, ln, 1);
        ln += __shfl_xor_sync(0xFFFFFFFFu, ln, 2);
        if (q == 0) {
            lg += bg[e]; ln += bn[e];
            float sp = (ln > 20.f) ? ln : log1pf(expf(ln));
            s_noisy[b][e] = lg + noise[b * E + e] * sp;
        }
    }
    __syncthreads();
    if (t < B) {
        float v1 = -INFINITY; int i1 = -1;
        #pragma unroll
        for (int e = 0; e < E; ++e) { float v = s_noisy[t][e]; if (v > v1) { v1 = v; i1 = e; } }
        float v2 = -INFINITY; int i2 = -1;
        #pragma unroll
        for (int e = 0; e < E; ++e) { if (e == i1) continue; float v = s_noisy[t][e]; if (v > v2) { v2 = v; i2 = e; } }
        float g1 = 1.f / (1.f + expf(v2 - v1));
        s_fe[t * TOPK + 0] = i1; s_fg[t * TOPK + 0] = g1;
        s_fe[t * TOPK + 1] = i2; s_fg[t * TOPK + 1] = 1.f - g1;
    }
    __syncthreads();
    if (t == 0) {
        int cnt[E];
        #pragma unroll
        for (int e = 0; e < E; ++e) cnt[e] = 0;
        for (int p = 0; p < NPAIR; ++p) {
            int e = s_fe[p];
            int c = cnt[e]++;
            if (c < CAP) { g_sample[e * CAP + c] = p / TOPK; g_gate[e * CAP + c] = s_fg[p]; }
        }
        #pragma unroll
        for (int e = 0; e < E; ++e) g_count[e] = (cnt[e] < CAP) ? cnt[e] : CAP;
    }
}

// ---------------- conversion core: fp32 -> bf16 hi/lo ------------------------
__device__ __forceinline__ void conv_one(const float4* __restrict__ in,
                                         uint4* __restrict__ oh,
                                         uint4* __restrict__ ol, size_t i) {
    float4 v0 = __ldcs(&in[2 * i]), v1 = __ldcs(&in[2 * i + 1]);
    float f[8] = {v0.x, v0.y, v0.z, v0.w, v1.x, v1.y, v1.z, v1.w};
    uint32_t H[4], L[4];
    #pragma unroll
    for (int p = 0; p < 4; ++p) {
        __nv_bfloat16 h0 = __float2bfloat16(f[2*p]);
        __nv_bfloat16 h1 = __float2bfloat16(f[2*p+1]);
        __nv_bfloat162 hp{h0, h1};
        __nv_bfloat162 lp{__float2bfloat16(f[2*p]   - __bfloat162float(h0)),
                          __float2bfloat16(f[2*p+1] - __bfloat162float(h1))};
        H[p] = *reinterpret_cast<uint32_t*>(&hp);
        L[p] = *reinterpret_cast<uint32_t*>(&lp);
    }
    __stcs(&oh[i], make_uint4(H[0], H[1], H[2], H[3]));
    __stcs(&ol[i], make_uint4(L[0], L[1], L[2], L[3]));
}

__global__ void conv_split(const float4* __restrict__ in,
                           uint4* __restrict__ oh,
                           uint4* __restrict__ ol, size_t n16) {
    size_t i = (size_t)blockIdx.x * blockDim.x + threadIdx.x;
    size_t stride = (size_t)gridDim.x * blockDim.x;
    for (; i < n16; i += stride) conv_one(in, oh, ol, i);
}

// fused: convert buffer0 (x) then buffer1 (W1) in one launch
__global__ void conv_split2(const float4* __restrict__ in0, uint4* __restrict__ oh0,
                            uint4* __restrict__ ol0, size_t n0,
                            const float4* __restrict__ in1, uint4* __restrict__ oh1,
                            uint4* __restrict__ ol1, size_t n1) {
    size_t i = (size_t)blockIdx.x * blockDim.x + threadIdx.x;
    size_t stride = (size_t)gridDim.x * blockDim.x;
    const size_t total = n0 + n1;
    for (; i < total; i += stride) {
        if (i < n0) conv_one(in0, oh0, ol0, i);
        else        conv_one(in1, oh1, ol1, i - n0);
    }
}

// ---------------- HMMA grouped GEMM (R10/R12: 4-stage, wait<=2) --------------
// CTA: 512 thr (16 warps as 4M x 4N), tile 128(M) x 256(N), K chunks of 32.
// 3-way bf16 split: Ah*Bh + Ah*Bl + Al*Bh, fp32 register accumulators.
// G1 additionally zeroes the output buffer (hidden under cp.async prefetch).
template<bool G1>
__global__ void __launch_bounds__(512, 1) moe_gemm(
    const float* __restrict__ bias, float* __restrict__ out) {
    const int tid = threadIdx.x;

    if (G1) {
        float4* o4 = reinterpret_cast<float4*>(out);
        const size_t nthr = (size_t)gridDim.x * gridDim.y * gridDim.z * 512;
        size_t gtid = ((size_t)((blockIdx.z * gridDim.y + blockIdx.y) * gridDim.x
                                + blockIdx.x)) * 512 + tid;
        const size_t n4 = (size_t)B * S * DIM / 4;
        for (size_t i = gtid; i < n4; i += nthr)
            o4[i] = make_float4(0.f, 0.f, 0.f, 0.f);
    }

    const int e    = blockIdx.z;
    const int mt   = blockIdx.y;
    const int slot = mt >> 2;
    if (slot >= g_count[e]) return;
    const int token0 = (mt & 3) * 128;
    const int n0     = blockIdx.x * NT;
    const int sample = g_sample[e * CAP + slot];

    const int KS = G1 ? DIM : HID;   // A row length (K)
    const int NS = G1 ? HID : DIM;   // B row length (N)
    const int C  = KS / KC;

    const size_t arow0 = G1 ? ((size_t)sample * S + token0)
                            : ((size_t)(e * CAP + slot) * S + token0);
    const __nv_bfloat16* Ah = (G1 ? g_xc_hi : g_h_hi) + arow0 * KS;
    const __nv_bfloat16* Al = (G1 ? g_xc_lo : g_h_lo) + arow0 * KS;
    const __nv_bfloat16* Bh = (G1 ? g_w1_hi : g_w2_hi) + (size_t)e * KS * NS;
    const __nv_bfloat16* Bl = (G1 ? g_w1_lo : g_w2_lo) + (size_t)e * KS * NS;

    extern __shared__ __align__(128) char smem_raw[];
    const uint32_t sb = smem_u32(smem_raw);
    const int w = tid >> 5, lane = tid & 31;
    const int wm = w & 3, wn = w >> 2;

    // ---- chunk loader: 3072 cp16 ops (A 1024, B 2048), 6 per thread --------
    auto load_chunk = [&](int c, int s_) {
        const int k0 = c * KC;
        const uint32_t base = sb + s_ * STAGE;
        #pragma unroll
        for (int j = 0; j < 6; ++j) {
            int i = tid + j * 512;
            if (i < 1024) {                    // A: 2(sub) x 128 rows x 4 segs
                int sub = i >> 9, idx = i & 511;
                int row = idx >> 2, seg = idx & 3;
                const __nv_bfloat16* src = (sub ? Al : Ah) + (size_t)row * KS + k0 + seg * 8;
                cp16(base + sub * A_MAT + row * A_STRIDE + seg * 16, src);
            } else {                           // B: 2(sub) x 32 rows x 32 segs
                int j2 = i - 1024;
                int sub = j2 >> 10, idx = j2 & 1023;
                int row = idx >> 5, seg = idx & 31;
                const __nv_bfloat16* src = (sub ? Bl : Bh) + (size_t)(k0 + row) * NS + n0 + seg * 8;
                cp16(base + A_SZ + sub * B_MAT + row * B_STRIDE + seg * 16, src);
            }
        }
        CP_COMMIT();
    };

    float acc[2][8][4];
    #pragma unroll
    for (int mi = 0; mi < 2; ++mi)
        #pragma unroll
        for (int nb = 0; nb < 8; ++nb)
            #pragma unroll
            for (int q = 0; q < 4; ++q) acc[mi][nb][q] = 0.f;

    load_chunk(0, 0);
    load_chunk(1, 1);
    load_chunk(2, 2);

    const uint32_t aLane = (wm * 32 + (lane & 15)) * A_STRIDE + (lane >> 4) * 16;
    const uint32_t bLane = A_SZ + (lane & 15) * B_STRIDE + (wn * 64 + (lane >> 4) * 8) * 2;

    for (int c = 0; c < C; ++c) {
        const int s_ = c & (NSTAGE - 1);
        if (c <= C - 3)      { CP_WAIT_2(); }
        else if (c == C - 2) { CP_WAIT_1(); }
        else                 { CP_WAIT_0(); }
        __syncthreads();
        const uint32_t base = sb + s_ * STAGE;
        #pragma unroll
        for (int ks = 0; ks < 2; ++ks) {
            uint32_t ah[2][4], al[2][4];
            #pragma unroll
            for (int mi = 0; mi < 2; ++mi) {
                uint32_t a = base + aLane + ks * 32 + mi * 16 * A_STRIDE;
                ldsm_x4(a, ah[mi]);
                ldsm_x4(a + A_MAT, al[mi]);
            }
            #pragma unroll
            for (int nb2 = 0; nb2 < 4; ++nb2) {
                uint32_t bh[4], bl[4];
                uint32_t a = base + bLane + ks * 16 * B_STRIDE + nb2 * 32;
                ldsm_x4t(a, bh);
                ldsm_x4t(a + B_MAT, bl);
                #pragma unroll
                for (int mi = 0; mi < 2; ++mi)
                    #pragma unroll
                    for (int h = 0; h < 2; ++h) {
                        float* ac = acc[mi][nb2 * 2 + h];
                        mma16816(ac, ah[mi], bh[h * 2], bh[h * 2 + 1]);
                        mma16816(ac, ah[mi], bl[h * 2], bl[h * 2 + 1]);
                        mma16816(ac, al[mi], bh[h * 2], bh[h * 2 + 1]);
                    }
            }
        }
        if (c + 3 < C) load_chunk(c + 3, (c + 3) & (NSTAGE - 1));
    }

    // ---- epilogue ----
    const int rbase = wm * 32 + (lane >> 2);
    const float gate = G1 ? 0.f : g_gate[e * CAP + slot];
    #pragma unroll
    for (int mi = 0; mi < 2; ++mi) {
        #pragma unroll
        for (int nb = 0; nb < 8; ++nb) {
            const int nc = wn * 64 + nb * 8 + (lane & 3) * 2;
            const float bx = bias[(size_t)e * NS + n0 + nc];
            const float by = bias[(size_t)e * NS + n0 + nc + 1];
            #pragma unroll
            for (int rr = 0; rr < 2; ++rr) {
                const int row = rbase + mi * 16 + rr * 8;
                float v0 = acc[mi][nb][rr * 2 + 0] + bx;
                float v1 = acc[mi][nb][rr * 2 + 1] + by;
                if (G1) {
                    // exact GELU: v * Phi(v)  (Phi == 0.5*(1+erf(v/sqrt2)))
                    v0 = v0 * normcdff(v0);
                    v1 = v1 * normcdff(v1);
                    __nv_bfloat16 h0 = __float2bfloat16(v0), h1 = __float2bfloat16(v1);
                    size_t off = ((size_t)(e * CAP + slot) * S + token0 + row) * HID + n0 + nc;
                    *reinterpret_cast<__nv_bfloat162*>(g_h_hi + off) = __nv_bfloat162{h0, h1};
                    *reinterpret_cast<__nv_bfloat162*>(g_h_lo + off) = __nv_bfloat162{
                        __float2bfloat16(v0 - __bfloat162float(h0)),
                        __float2bfloat16(v1 - __bfloat162float(h1))};
                } else {
                    float* dst = out + ((size_t)sample * S + token0 + row) * DIM + n0 + nc;
                    red_add_v2(dst, v0 * gate, v1 * gate);
                }
            }
        }
    }
}

// ---------------- launch ------------------------------------------------------
extern "C" void kernel_launch(void* const* d_in, const int* in_sizes, int n_in,
                              void* d_out, int out_size) {
    const float* rin   = (const float*)d_in[0];
    const float* x     = (const float*)d_in[1];
    const float* noise = (const float*)d_in[2];
    const float* Wg    = (const float*)d_in[3];
    const float* bg    = (const float*)d_in[4];
    const float* Wn    = (const float*)d_in[5];
    const float* bn    = (const float*)d_in[6];
    const float* W1    = (const float*)d_in[7];
    const float* b1    = (const float*)d_in[8];
    const float* W2    = (const float*)d_in[9];
    const float* b2    = (const float*)d_in[10];
    float* out = (float*)d_out;

    struct Res {
        cudaStream_t s2;
        cudaEvent_t ev_fork, ev_router, ev_cw1, ev_w2;
        Res() {
            cudaStreamCreateWithFlags(&s2, cudaStreamNonBlocking);
            cudaEventCreateWithFlags(&ev_fork,   cudaEventDisableTiming);
            cudaEventCreateWithFlags(&ev_router, cudaEventDisableTiming);
            cudaEventCreateWithFlags(&ev_cw1,    cudaEventDisableTiming);
            cudaEventCreateWithFlags(&ev_w2,     cudaEventDisableTiming);
            cudaFuncSetAttribute(moe_gemm<true>,
                cudaFuncAttributeMaxDynamicSharedMemorySize, SMEM_DYN);
            cudaFuncSetAttribute(moe_gemm<false>,
                cudaFuncAttributeMaxDynamicSharedMemorySize, SMEM_DYN);
        }
    };
    static Res R;

    uint4 *xh, *xl, *w1h, *w1l, *w2h, *w2l;
    cudaGetSymbolAddress((void**)&xh,  g_xc_hi);
    cudaGetSymbolAddress((void**)&xl,  g_xc_lo);
    cudaGetSymbolAddress((void**)&w1h, g_w1_hi);
    cudaGetSymbolAddress((void**)&w1l, g_w1_lo);
    cudaGetSymbolAddress((void**)&w2h, g_w2_hi);
    cudaGetSymbolAddress((void**)&w2l, g_w2_lo);

    // fork side stream from the default (capture) stream
    cudaEventRecord(R.ev_fork, 0);
    cudaStreamWaitEvent(R.s2, R.ev_fork, 0);

    // side: ri -> router (gemm1 gating metadata)
    ri_kernel<<<(B * DIM + 255) / 256, 256, 0, R.s2>>>(rin);
    router_kernel<<<1, 1024, 0, R.s2>>>(noise, Wg, bg, Wn, bn);
    cudaEventRecord(R.ev_router, R.s2);

    // main: fused conv_x + conv_w1 (one launch, same bytes)
    conv_split2<<<8192, 256>>>((const float4*)x,  xh,  xl,  (size_t)B * S * DIM / 8,
                               (const float4*)W1, w1h, w1l, (size_t)E * DIM * HID / 8);
    cudaEventRecord(R.ev_cw1, 0);

    // side: conv_w2 after main convs (overlaps gemm1, whose DRAM is idle)
    cudaStreamWaitEvent(R.s2, R.ev_cw1, 0);
    conv_split<<<8192, 256, 0, R.s2>>>((const float4*)W2, w2h, w2l, (size_t)E * HID * DIM / 8);
    cudaEventRecord(R.ev_w2, R.s2);

    // main: gemm1 (needs router metadata; also zeroes out), then gemm2
    cudaStreamWaitEvent(0, R.ev_router, 0);
    moe_gemm<true ><<<dim3(HID / NT, 32, E), 512, SMEM_DYN>>>(b1, out);
    cudaStreamWaitEvent(0, R.ev_w2, 0);
    moe_gemm<false><<<dim3(DIM / NT, 32, E), 512, SMEM_DYN>>>(b2, out);
}

// round 14
// speedup vs baseline: 1.0270x; 1.0270x over previous
#include <cuda_runtime.h>
#include <cuda_bf16.h>
#include <math.h>
#include <stdint.h>

#define B    32
#define S    512
#define DIM  1024
#define HID  4096
#define E    8
#define TOPK 2
#define CAP  8
#define NPAIR (B*TOPK)

#define KC   32                 // K chunk (bf16 elems)
#define NT   256                // N tile
#define A_STRIDE 80             // bytes per A row in smem
#define B_STRIDE 528            // bytes per B row in smem (256*2 padded)
#define A_MAT   10240           // 128 rows * 80B
#define B_MAT   16896           // 32 rows * 528B
#define A_SZ    20480           // 2 * A_MAT
#define STAGE   54272           // A hi/lo + B hi/lo
#define NSTAGE  4
#define SMEM_DYN (NSTAGE * STAGE)

// ---------------- device scratch -------------------------------------------
__device__ float g_ri[B * DIM];
__device__ int   g_sample[E * CAP];
__device__ float g_gate[E * CAP];
__device__ int   g_count[E];
__device__ __nv_bfloat16 g_xc_hi[(size_t)B * S * DIM];
__device__ __nv_bfloat16 g_xc_lo[(size_t)B * S * DIM];
__device__ __nv_bfloat16 g_w1_hi[(size_t)E * DIM * HID];   // [e][k][n]
__device__ __nv_bfloat16 g_w1_lo[(size_t)E * DIM * HID];
__device__ __nv_bfloat16 g_w2_hi[(size_t)E * HID * DIM];   // [e][k][n]
__device__ __nv_bfloat16 g_w2_lo[(size_t)E * HID * DIM];
__device__ __nv_bfloat16 g_h_hi[(size_t)E * CAP * S * HID];
__device__ __nv_bfloat16 g_h_lo[(size_t)E * CAP * S * HID];

// ---------------- PTX helpers ----------------------------------------------
__device__ __forceinline__ uint32_t smem_u32(const void* p) {
    uint32_t a;
    asm("{ .reg .u64 t; cvta.to.shared.u64 t, %1; cvt.u32.u64 %0, t; }" : "=r"(a) : "l"(p));
    return a;
}
__device__ __forceinline__ void cp16(uint32_t dst, const void* src) {
    asm volatile("cp.async.cg.shared.global [%0], [%1], 16;" :: "r"(dst), "l"(src));
}
#define CP_COMMIT()  asm volatile("cp.async.commit_group;" ::: "memory")
#define CP_WAIT_2()  asm volatile("cp.async.wait_group 2;" ::: "memory")
#define CP_WAIT_1()  asm volatile("cp.async.wait_group 1;" ::: "memory")
#define CP_WAIT_0()  asm volatile("cp.async.wait_group 0;" ::: "memory")

__device__ __forceinline__ void ldsm_x4(uint32_t a, uint32_t r[4]) {
    asm volatile("ldmatrix.sync.aligned.m8n8.x4.shared.b16 {%0,%1,%2,%3}, [%4];"
                 : "=r"(r[0]), "=r"(r[1]), "=r"(r[2]), "=r"(r[3]) : "r"(a));
}
__device__ __forceinline__ void ldsm_x4t(uint32_t a, uint32_t r[4]) {
    asm volatile("ldmatrix.sync.aligned.m8n8.x4.trans.shared.b16 {%0,%1,%2,%3}, [%4];"
                 : "=r"(r[0]), "=r"(r[1]), "=r"(r[2]), "=r"(r[3]) : "r"(a));
}
__device__ __forceinline__ void mma16816(float c[4], const uint32_t a[4],
                                         uint32_t b0, uint32_t b1) {
    asm volatile("mma.sync.aligned.m16n8k16.row.col.f32.bf16.bf16.f32 "
                 "{%0,%1,%2,%3},{%4,%5,%6,%7},{%8,%9},{%0,%1,%2,%3};"
                 : "+f"(c[0]), "+f"(c[1]), "+f"(c[2]), "+f"(c[3])
                 : "r"(a[0]), "r"(a[1]), "r"(a[2]), "r"(a[3]), "r"(b0), "r"(b1));
}
__device__ __forceinline__ void red_add_v2(float* p, float v0, float v1) {
    asm volatile("red.global.add.v2.f32 [%0], {%1, %2};"
                 :: "l"(p), "f"(v0), "f"(v1) : "memory");
}

// ---------------- kernel: ri = mean over sequence ---------------------------
__global__ void ri_kernel(const float* __restrict__ rin) {
    int idx = blockIdx.x * blockDim.x + threadIdx.x;
    if (idx >= B * DIM) return;
    int b = idx / DIM, d = idx % DIM;
    const float* p = rin + (size_t)b * S * DIM + d;
    float acc = 0.f;
    #pragma unroll 8
    for (int s = 0; s < S; ++s) acc += p[(size_t)s * DIM];
    g_ri[idx] = acc * (1.0f / S);
}

// ---------------- kernel: router + top-2 + capacity (1024 thr) --------------
__global__ void __launch_bounds__(1024) router_kernel(
        const float* __restrict__ noise,
        const float* __restrict__ Wg, const float* __restrict__ bg,
        const float* __restrict__ Wn, const float* __restrict__ bn) {
    __shared__ float s_noisy[B][E];
    __shared__ int   s_fe[NPAIR];
    __shared__ float s_fg[NPAIR];
    const int t = threadIdx.x;
    {
        const int pair = t >> 2, q = t & 3;
        const int b = pair / E, e = pair % E;
        const float* ri = g_ri + b * DIM + q * 256;
        float lg = 0.f, ln = 0.f;
        #pragma unroll 8
        for (int d = 0; d < 256; ++d) {
            float r = ri[d];
            int col = (q * 256 + d) * E + e;
            lg = fmaf(r, Wg[col], lg);
            ln = fmaf(r, Wn[col], ln);
        }
        lg += __shfl_xor_sync(0xFFFFFFFFu, lg, 1);
        lg += __shfl_xor_sync(0xFFFFFFFFu, lg, 2);
        ln += __shfl_xor_sync(0xFFFFFFFFu, ln, 1);
        ln += __shfl_xor_sync(0xFFFFFFFFu, ln, 2);
        if (q == 0) {
            lg += bg[e]; ln += bn[e];
            float sp = (ln > 20.f) ? ln : log1pf(expf(ln));
            s_noisy[b][e] = lg + noise[b * E + e] * sp;
        }
    }
    __syncthreads();
    if (t < B) {
        float v1 = -INFINITY; int i1 = -1;
        #pragma unroll
        for (int e = 0; e < E; ++e) { float v = s_noisy[t][e]; if (v > v1) { v1 = v; i1 = e; } }
        float v2 = -INFINITY; int i2 = -1;
        #pragma unroll
        for (int e = 0; e < E; ++e) { if (e == i1) continue; float v = s_noisy[t][e]; if (v > v2) { v2 = v; i2 = e; } }
        float g1 = 1.f / (1.f + expf(v2 - v1));
        s_fe[t * TOPK + 0] = i1; s_fg[t * TOPK + 0] = g1;
        s_fe[t * TOPK + 1] = i2; s_fg[t * TOPK + 1] = 1.f - g1;
    }
    __syncthreads();
    if (t == 0) {
        int cnt[E];
        #pragma unroll
        for (int e = 0; e < E; ++e) cnt[e] = 0;
        for (int p = 0; p < NPAIR; ++p) {
            int e = s_fe[p];
            int c = cnt[e]++;
            if (c < CAP) { g_sample[e * CAP + c] = p / TOPK; g_gate[e * CAP + c] = s_fg[p]; }
        }
        #pragma unroll
        for (int e = 0; e < E; ++e) g_count[e] = (cnt[e] < CAP) ? cnt[e] : CAP;
    }
}

// ---------------- conversion core: fp32 -> bf16 hi/lo ------------------------
__device__ __forceinline__ void conv_one(const float4* __restrict__ in,
                                         uint4* __restrict__ oh,
                                         uint4* __restrict__ ol, size_t i) {
    float4 v0 = __ldcs(&in[2 * i]), v1 = __ldcs(&in[2 * i + 1]);
    float f[8] = {v0.x, v0.y, v0.z, v0.w, v1.x, v1.y, v1.z, v1.w};
    uint32_t H[4], L[4];
    #pragma unroll
    for (int p = 0; p < 4; ++p) {
        __nv_bfloat16 h0 = __float2bfloat16(f[2*p]);
        __nv_bfloat16 h1 = __float2bfloat16(f[2*p+1]);
        __nv_bfloat162 hp{h0, h1};
        __nv_bfloat162 lp{__float2bfloat16(f[2*p]   - __bfloat162float(h0)),
                          __float2bfloat16(f[2*p+1] - __bfloat162float(h1))};
        H[p] = *reinterpret_cast<uint32_t*>(&hp);
        L[p] = *reinterpret_cast<uint32_t*>(&lp);
    }
    __stcs(&oh[i], make_uint4(H[0], H[1], H[2], H[3]));
    __stcs(&ol[i], make_uint4(L[0], L[1], L[2], L[3]));
}

__global__ void conv_split(const float4* __restrict__ in,
                           uint4* __restrict__ oh,
                           uint4* __restrict__ ol, size_t n16) {
    size_t i = (size_t)blockIdx.x * blockDim.x + threadIdx.x;
    size_t stride = (size_t)gridDim.x * blockDim.x;
    for (; i < n16; i += stride) conv_one(in, oh, ol, i);
}

// fused: convert buffer0 (x) then buffer1 (W1) in one launch
__global__ void conv_split2(const float4* __restrict__ in0, uint4* __restrict__ oh0,
                            uint4* __restrict__ ol0, size_t n0,
                            const float4* __restrict__ in1, uint4* __restrict__ oh1,
                            uint4* __restrict__ ol1, size_t n1) {
    size_t i = (size_t)blockIdx.x * blockDim.x + threadIdx.x;
    size_t stride = (size_t)gridDim.x * blockDim.x;
    const size_t total = n0 + n1;
    for (; i < total; i += stride) {
        if (i < n0) conv_one(in0, oh0, ol0, i);
        else        conv_one(in1, oh1, ol1, i - n0);
    }
}

// ---------------- HMMA grouped GEMM (R12: 4-stage, wait<=2) ------------------
// CTA: 512 thr (16 warps as 4M x 4N), tile 128(M) x 256(N), K chunks of 32.
// 3-way bf16 split: Ah*Bh + Ah*Bl + Al*Bh, fp32 register accumulators.
// G1 additionally zeroes the output buffer (hidden under cp.async prefetch).
template<bool G1>
__global__ void __launch_bounds__(512, 1) moe_gemm(
    const float* __restrict__ bias, float* __restrict__ out) {
    const int tid = threadIdx.x;

    if (G1) {
        float4* o4 = reinterpret_cast<float4*>(out);
        const size_t nthr = (size_t)gridDim.x * gridDim.y * gridDim.z * 512;
        size_t gtid = ((size_t)((blockIdx.z * gridDim.y + blockIdx.y) * gridDim.x
                                + blockIdx.x)) * 512 + tid;
        const size_t n4 = (size_t)B * S * DIM / 4;
        for (size_t i = gtid; i < n4; i += nthr)
            o4[i] = make_float4(0.f, 0.f, 0.f, 0.f);
    }

    const int e    = blockIdx.z;
    const int mt   = blockIdx.y;
    const int slot = mt >> 2;
    if (slot >= g_count[e]) return;
    const int token0 = (mt & 3) * 128;
    const int n0     = blockIdx.x * NT;
    const int sample = g_sample[e * CAP + slot];

    const int KS = G1 ? DIM : HID;   // A row length (K)
    const int NS = G1 ? HID : DIM;   // B row length (N)
    const int C  = KS / KC;

    const size_t arow0 = G1 ? ((size_t)sample * S + token0)
                            : ((size_t)(e * CAP + slot) * S + token0);
    const __nv_bfloat16* Ah = (G1 ? g_xc_hi : g_h_hi) + arow0 * KS;
    const __nv_bfloat16* Al = (G1 ? g_xc_lo : g_h_lo) + arow0 * KS;
    const __nv_bfloat16* Bh = (G1 ? g_w1_hi : g_w2_hi) + (size_t)e * KS * NS;
    const __nv_bfloat16* Bl = (G1 ? g_w1_lo : g_w2_lo) + (size_t)e * KS * NS;

    extern __shared__ __align__(128) char smem_raw[];
    const uint32_t sb = smem_u32(smem_raw);
    const int w = tid >> 5, lane = tid & 31;
    const int wm = w & 3, wn = w >> 2;

    // ---- chunk loader: 3072 cp16 ops (A 1024, B 2048), 6 per thread --------
    auto load_chunk = [&](int c, int s_) {
        const int k0 = c * KC;
        const uint32_t base = sb + s_ * STAGE;
        #pragma unroll
        for (int j = 0; j < 6; ++j) {
            int i = tid + j * 512;
            if (i < 1024) {                    // A: 2(sub) x 128 rows x 4 segs
                int sub = i >> 9, idx = i & 511;
                int row = idx >> 2, seg = idx & 3;
                const __nv_bfloat16* src = (sub ? Al : Ah) + (size_t)row * KS + k0 + seg * 8;
                cp16(base + sub * A_MAT + row * A_STRIDE + seg * 16, src);
            } else {                           // B: 2(sub) x 32 rows x 32 segs
                int j2 = i - 1024;
                int sub = j2 >> 10, idx = j2 & 1023;
                int row = idx >> 5, seg = idx & 31;
                const __nv_bfloat16* src = (sub ? Bl : Bh) + (size_t)(k0 + row) * NS + n0 + seg * 8;
                cp16(base + A_SZ + sub * B_MAT + row * B_STRIDE + seg * 16, src);
            }
        }
        CP_COMMIT();
    };

    float acc[2][8][4];
    #pragma unroll
    for (int mi = 0; mi < 2; ++mi)
        #pragma unroll
        for (int nb = 0; nb < 8; ++nb)
            #pragma unroll
            for (int q = 0; q < 4; ++q) acc[mi][nb][q] = 0.f;

    load_chunk(0, 0);
    load_chunk(1, 1);
    load_chunk(2, 2);

    const uint32_t aLane = (wm * 32 + (lane & 15)) * A_STRIDE + (lane >> 4) * 16;
    const uint32_t bLane = A_SZ + (lane & 15) * B_STRIDE + (wn * 64 + (lane >> 4) * 8) * 2;

    for (int c = 0; c < C; ++c) {
        const int s_ = c & (NSTAGE - 1);
        if (c <= C - 3)      { CP_WAIT_2(); }
        else if (c == C - 2) { CP_WAIT_1(); }
        else                 { CP_WAIT_0(); }
        __syncthreads();
        const uint32_t base = sb + s_ * STAGE;
        #pragma unroll
        for (int ks = 0; ks < 2; ++ks) {
            uint32_t ah[2][4], al[2][4];
            #pragma unroll
            for (int mi = 0; mi < 2; ++mi) {
                uint32_t a = base + aLane + ks * 32 + mi * 16 * A_STRIDE;
                ldsm_x4(a, ah[mi]);
                ldsm_x4(a + A_MAT, al[mi]);
            }
            #pragma unroll
            for (int nb2 = 0; nb2 < 4; ++nb2) {
                uint32_t bh[4], bl[4];
                uint32_t a = base + bLane + ks * 16 * B_STRIDE + nb2 * 32;
                ldsm_x4t(a, bh);
                ldsm_x4t(a + B_MAT, bl);
                #pragma unroll
                for (int mi = 0; mi < 2; ++mi)
                    #pragma unroll
                    for (int h = 0; h < 2; ++h) {
                        float* ac = acc[mi][nb2 * 2 + h];
                        mma16816(ac, ah[mi], bh[h * 2], bh[h * 2 + 1]);
                        mma16816(ac, ah[mi], bl[h * 2], bl[h * 2 + 1]);
                        mma16816(ac, al[mi], bh[h * 2], bh[h * 2 + 1]);
                    }
            }
        }
        if (c + 3 < C) load_chunk(c + 3, (c + 3) & (NSTAGE - 1));
    }

    // ---- epilogue ----
    const int rbase = wm * 32 + (lane >> 2);
    const float gate = G1 ? 0.f : g_gate[e * CAP + slot];
    #pragma unroll
    for (int mi = 0; mi < 2; ++mi) {
        #pragma unroll
        for (int nb = 0; nb < 8; ++nb) {
            const int nc = wn * 64 + nb * 8 + (lane & 3) * 2;
            const float bx = bias[(size_t)e * NS + n0 + nc];
            const float by = bias[(size_t)e * NS + n0 + nc + 1];
            #pragma unroll
            for (int rr = 0; rr < 2; ++rr) {
                const int row = rbase + mi * 16 + rr * 8;
                float v0 = acc[mi][nb][rr * 2 + 0] + bx;
                float v1 = acc[mi][nb][rr * 2 + 1] + by;
                if (G1) {
                    v0 = 0.5f * v0 * (1.0f + erff(v0 * 0.70710678118654752f));
                    v1 = 0.5f * v1 * (1.0f + erff(v1 * 0.70710678118654752f));
                    __nv_bfloat16 h0 = __float2bfloat16(v0), h1 = __float2bfloat16(v1);
                    size_t off = ((size_t)(e * CAP + slot) * S + token0 + row) * HID + n0 + nc;
                    *reinterpret_cast<__nv_bfloat162*>(g_h_hi + off) = __nv_bfloat162{h0, h1};
                    *reinterpret_cast<__nv_bfloat162*>(g_h_lo + off) = __nv_bfloat162{
                        __float2bfloat16(v0 - __bfloat162float(h0)),
                        __float2bfloat16(v1 - __bfloat162float(h1))};
                } else {
                    float* dst = out + ((size_t)sample * S + token0 + row) * DIM + n0 + nc;
                    red_add_v2(dst, v0 * gate, v1 * gate);
                }
            }
        }
    }
}

// ---------------- launch ------------------------------------------------------
extern "C" void kernel_launch(void* const* d_in, const int* in_sizes, int n_in,
                              void* d_out, int out_size) {
    const float* rin   = (const float*)d_in[0];
    const float* x     = (const float*)d_in[1];
    const float* noise = (const float*)d_in[2];
    const float* Wg    = (const float*)d_in[3];
    const float* bg    = (const float*)d_in[4];
    const float* Wn    = (const float*)d_in[5];
    const float* bn    = (const float*)d_in[6];
    const float* W1    = (const float*)d_in[7];
    const float* b1    = (const float*)d_in[8];
    const float* W2    = (const float*)d_in[9];
    const float* b2    = (const float*)d_in[10];
    float* out = (float*)d_out;

    struct Res {
        cudaStream_t s2;
        cudaEvent_t ev_fork, ev_router, ev_cw1, ev_w2;
        Res() {
            cudaStreamCreateWithFlags(&s2, cudaStreamNonBlocking);
            cudaEventCreateWithFlags(&ev_fork,   cudaEventDisableTiming);
            cudaEventCreateWithFlags(&ev_router, cudaEventDisableTiming);
            cudaEventCreateWithFlags(&ev_cw1,    cudaEventDisableTiming);
            cudaEventCreateWithFlags(&ev_w2,     cudaEventDisableTiming);
            cudaFuncSetAttribute(moe_gemm<true>,
                cudaFuncAttributeMaxDynamicSharedMemorySize, SMEM_DYN);
            cudaFuncSetAttribute(moe_gemm<false>,
                cudaFuncAttributeMaxDynamicSharedMemorySize, SMEM_DYN);
        }
    };
    static Res R;

    uint4 *xh, *xl, *w1h, *w1l, *w2h, *w2l;
    cudaGetSymbolAddress((void**)&xh,  g_xc_hi);
    cudaGetSymbolAddress((void**)&xl,  g_xc_lo);
    cudaGetSymbolAddress((void**)&w1h, g_w1_hi);
    cudaGetSymbolAddress((void**)&w1l, g_w1_lo);
    cudaGetSymbolAddress((void**)&w2h, g_w2_hi);
    cudaGetSymbolAddress((void**)&w2l, g_w2_lo);

    // fork side stream from the default (capture) stream
    cudaEventRecord(R.ev_fork, 0);
    cudaStreamWaitEvent(R.s2, R.ev_fork, 0);

    // side: ri -> router (gemm1 gating metadata)
    ri_kernel<<<(B * DIM + 255) / 256, 256, 0, R.s2>>>(rin);
    router_kernel<<<1, 1024, 0, R.s2>>>(noise, Wg, bg, Wn, bn);
    cudaEventRecord(R.ev_router, R.s2);

    // main: fused conv_x + conv_w1 (one launch, same bytes)
    conv_split2<<<8192, 256>>>((const float4*)x,  xh,  xl,  (size_t)B * S * DIM / 8,
                               (const float4*)W1, w1h, w1l, (size_t)E * DIM * HID / 8);
    cudaEventRecord(R.ev_cw1, 0);

    // side: conv_w2 after main convs (overlaps gemm1, whose DRAM is idle)
    cudaStreamWaitEvent(R.s2, R.ev_cw1, 0);
    conv_split<<<8192, 256, 0, R.s2>>>((const float4*)W2, w2h, w2l, (size_t)E * HID * DIM / 8);
    cudaEventRecord(R.ev_w2, R.s2);

    // main: gemm1 (needs router metadata; also zeroes out), then gemm2
    cudaStreamWaitEvent(0, R.ev_router, 0);
    moe_gemm<true ><<<dim3(HID / NT, 32, E), 512, SMEM_DYN>>>(b1, out);
    cudaStreamWaitEvent(0, R.ev_w2, 0);
    moe_gemm<false><<<dim3(DIM / NT, 32, E), 512, SMEM_DYN>>>(b2, out);
}